// round 2
// baseline (speedup 1.0000x reference)
#include <cuda_runtime.h>
#include <math.h>

// Problem constants
#define NL 4
#define NH 8
#define DM 512
#define HD 64
#define TT 2048
#define BB 2
#define VV 32000
#define BT (BB*TT)          // 4096 rows
#define EPSF 1e-5f

// ---------------------------------------------------------------------------
// Scratch (device globals; no runtime allocation allowed)
// ---------------------------------------------------------------------------
__device__ float g_x[BT * DM];            // residual stream
__device__ float g_h[BT * DM];            // layernorm output
__device__ float g_qkv[BT * 3 * DM];      // qkv projections
__device__ float g_y[BT * DM];            // attention output
__device__ float g_ffn[BT * 4 * DM];      // MLP hidden
__device__ float g_wteT[(size_t)DM * VV]; // transposed embedding for lm head

// ---------------------------------------------------------------------------
// Embedding: x[b,t,:] = wte[idx[b,t],:] + wpe[t,:]
// ---------------------------------------------------------------------------
__global__ void gpt_embed_kernel(const float* __restrict__ wte,
                                 const float* __restrict__ wpe,
                                 const int* __restrict__ idx) {
    int i = blockIdx.x * 256 + threadIdx.x;      // over BT*DM
    int d  = i & (DM - 1);
    int bt = i >> 9;                              // /512
    int t  = bt & (TT - 1);
    g_x[i] = wte[(size_t)idx[bt] * DM + d] + wpe[t * DM + d];
}

// ---------------------------------------------------------------------------
// Transpose wte [V,D] -> wteT [D,V]
// ---------------------------------------------------------------------------
__global__ void gpt_transpose_kernel(const float* __restrict__ in) {
    __shared__ float tile[32][33];
    int v0 = blockIdx.x * 32, d0 = blockIdx.y * 32;
    int tx = threadIdx.x, ty = threadIdx.y;       // (32, 8)
#pragma unroll
    for (int j = 0; j < 32; j += 8)
        tile[ty + j][tx] = in[(size_t)(v0 + ty + j) * DM + d0 + tx];
    __syncthreads();
#pragma unroll
    for (int j = 0; j < 32; j += 8)
        g_wteT[(size_t)(d0 + ty + j) * VV + v0 + tx] = tile[tx][ty + j];
}

// ---------------------------------------------------------------------------
// LayerNorm: one warp per row of 512 (float4 x 4 per lane)
// ---------------------------------------------------------------------------
__global__ void gpt_ln_kernel(const float* __restrict__ in,
                              const float* __restrict__ w,
                              const float* __restrict__ b,
                              float* __restrict__ out) {
    int row  = blockIdx.x * 8 + (threadIdx.x >> 5);
    int lane = threadIdx.x & 31;
    const float4* p = (const float4*)(in + (size_t)row * DM);
    float4 v[4];
    float s = 0.f, s2 = 0.f;
#pragma unroll
    for (int i = 0; i < 4; i++) {
        v[i] = p[lane + i * 32];
        s  += v[i].x + v[i].y + v[i].z + v[i].w;
        s2 += v[i].x * v[i].x + v[i].y * v[i].y + v[i].z * v[i].z + v[i].w * v[i].w;
    }
#pragma unroll
    for (int o = 16; o > 0; o >>= 1) {
        s  += __shfl_xor_sync(0xffffffffu, s,  o);
        s2 += __shfl_xor_sync(0xffffffffu, s2, o);
    }
    float mu  = s  * (1.f / DM);
    float var = s2 * (1.f / DM) - mu * mu;
    float r   = rsqrtf(var + EPSF);
    float4* o4 = (float4*)(out + (size_t)row * DM);
    const float4* w4 = (const float4*)w;
    const float4* b4 = (const float4*)b;
#pragma unroll
    for (int i = 0; i < 4; i++) {
        float4 wv = w4[lane + i * 32], bv = b4[lane + i * 32], xv = v[i], yv;
        yv.x = (xv.x - mu) * r * wv.x + bv.x;
        yv.y = (xv.y - mu) * r * wv.y + bv.y;
        yv.z = (xv.z - mu) * r * wv.z + bv.z;
        yv.w = (xv.w - mu) * r * wv.w + bv.w;
        o4[lane + i * 32] = yv;
    }
}

// ---------------------------------------------------------------------------
// SGEMM: C[M,N] = A[M,K] @ B[K,N] (+ bias / + resid / gelu)
// BM=BN=128, BK=16, 256 threads, 8x8 microtile, double-buffered smem with
// register-staged global prefetch. All dims divide 128/16 evenly.
// EPI: 0 = none, 1 = +bias, 2 = +bias +resid, 3 = gelu(+bias)
// ---------------------------------------------------------------------------
__device__ __forceinline__ float gelu_exact(float v) {
    return 0.5f * v * (1.0f + erff(v * 0.70710678118654752f));
}

template<int EPI>
__global__ void __launch_bounds__(256, 2)
gpt_gemm_kernel(const float* __restrict__ A, const float* __restrict__ B,
                const float* __restrict__ bias, const float* __restrict__ resid,
                float* __restrict__ C, int M, int N, int K) {
    constexpr int BM = 128, BN = 128, BK = 16, TM = 8, TN = 8;
    __shared__ float As[2][BK][BM];   // A stored k-major (transposed)
    __shared__ float Bs[2][BK][BN];
    int tid  = threadIdx.x;
    int cRow = blockIdx.y, cCol = blockIdx.x;
    const float* Ag = A + (size_t)cRow * BM * K;
    const float* Bg = B + (size_t)cCol * BN;

    // A tile load mapping: 128 rows x 16 cols, 2 float4 per thread
    int aRow = tid >> 1, aCol = (tid & 1) * 8;
    // B tile load mapping: 16 rows x 128 cols, 2 float4 per thread
    int bRow = tid >> 4, bCol = (tid & 15) * 8;
    // microtile
    int tRow = (tid >> 4) * TM, tCol = (tid & 15) * TN;

    float acc[TM][TN];
#pragma unroll
    for (int i = 0; i < TM; i++)
#pragma unroll
        for (int j = 0; j < TN; j++) acc[i][j] = 0.f;

    // ---- preload tile 0 into smem[0] ----
    {
        const float* ap = Ag + (size_t)aRow * K + aCol;
        float4 a0 = *(const float4*)(ap);
        float4 a1 = *(const float4*)(ap + 4);
        As[0][aCol + 0][aRow] = a0.x; As[0][aCol + 1][aRow] = a0.y;
        As[0][aCol + 2][aRow] = a0.z; As[0][aCol + 3][aRow] = a0.w;
        As[0][aCol + 4][aRow] = a1.x; As[0][aCol + 5][aRow] = a1.y;
        As[0][aCol + 6][aRow] = a1.z; As[0][aCol + 7][aRow] = a1.w;
        const float* bp = Bg + (size_t)bRow * N + bCol;
        *(float4*)(&Bs[0][bRow][bCol])     = *(const float4*)(bp);
        *(float4*)(&Bs[0][bRow][bCol + 4]) = *(const float4*)(bp + 4);
    }
    __syncthreads();

    int buf = 0;
    for (int k0 = 0; k0 < K; k0 += BK) {
        // ---- prefetch next tile into registers ----
        float4 pa0, pa1, pb0, pb1;
        bool more = (k0 + BK) < K;
        if (more) {
            const float* ap = Ag + (size_t)aRow * K + (k0 + BK) + aCol;
            pa0 = *(const float4*)(ap);
            pa1 = *(const float4*)(ap + 4);
            const float* bp = Bg + (size_t)(k0 + BK + bRow) * N + bCol;
            pb0 = *(const float4*)(bp);
            pb1 = *(const float4*)(bp + 4);
        }

        // ---- compute from smem[buf] ----
#pragma unroll
        for (int kk = 0; kk < BK; kk++) {
            float regA[TM], regB[TN];
            *(float4*)&regA[0] = *(const float4*)&As[buf][kk][tRow];
            *(float4*)&regA[4] = *(const float4*)&As[buf][kk][tRow + 4];
            *(float4*)&regB[0] = *(const float4*)&Bs[buf][kk][tCol];
            *(float4*)&regB[4] = *(const float4*)&Bs[buf][kk][tCol + 4];
#pragma unroll
            for (int i = 0; i < TM; i++)
#pragma unroll
                for (int j = 0; j < TN; j++)
                    acc[i][j] = fmaf(regA[i], regB[j], acc[i][j]);
        }

        // ---- store prefetched tile into the other buffer ----
        if (more) {
            int nb = buf ^ 1;
            As[nb][aCol + 0][aRow] = pa0.x; As[nb][aCol + 1][aRow] = pa0.y;
            As[nb][aCol + 2][aRow] = pa0.z; As[nb][aCol + 3][aRow] = pa0.w;
            As[nb][aCol + 4][aRow] = pa1.x; As[nb][aCol + 5][aRow] = pa1.y;
            As[nb][aCol + 6][aRow] = pa1.z; As[nb][aCol + 7][aRow] = pa1.w;
            *(float4*)(&Bs[nb][bRow][bCol])     = pb0;
            *(float4*)(&Bs[nb][bRow][bCol + 4]) = pb1;
            __syncthreads();
        }
        buf ^= 1;
    }

    // ---- epilogue ----
#pragma unroll
    for (int i = 0; i < TM; i++) {
        size_t m = (size_t)cRow * BM + tRow + i;
        float* Crow = C + m * N + (size_t)cCol * BN;
        const float* Rrow = (EPI == 2) ? (resid + m * N + (size_t)cCol * BN) : nullptr;
#pragma unroll
        for (int jj = 0; jj < TN; jj += 4) {
            int n = tCol + jj;
            float4 o;
            o.x = acc[i][jj + 0];
            o.y = acc[i][jj + 1];
            o.z = acc[i][jj + 2];
            o.w = acc[i][jj + 3];
            if (EPI >= 1) {
                float4 bv = *(const float4*)(bias + (size_t)cCol * BN + n);
                o.x += bv.x; o.y += bv.y; o.z += bv.z; o.w += bv.w;
            }
            if (EPI == 2) {
                float4 rv = *(const float4*)(Rrow + n);
                o.x += rv.x; o.y += rv.y; o.z += rv.z; o.w += rv.w;
            }
            if (EPI == 3) {
                o.x = gelu_exact(o.x); o.y = gelu_exact(o.y);
                o.z = gelu_exact(o.z); o.w = gelu_exact(o.w);
            }
            *(float4*)(Crow + n) = o;
        }
    }
}

// ---------------------------------------------------------------------------
// Causal attention, warp per query row, online softmax.
// qkv row layout: [q(0..511) | k(512..1023) | v(1024..1535)], head h at h*64.
// ---------------------------------------------------------------------------
__global__ void gpt_attn_kernel() {
    int gw   = (blockIdx.x * blockDim.x + threadIdx.x) >> 5;
    int lane = threadIdx.x & 31;
    int q  = gw & (TT - 1);
    int bh = gw >> 11;            // TT = 2048
    int h  = bh & (NH - 1);
    int b  = bh >> 3;

    const float* base = g_qkv + (size_t)b * TT * (3 * DM);
    const float* qrow = base + (size_t)q * (3 * DM) + h * HD;
    float q0 = qrow[lane], q1 = qrow[lane + 32];

    float m = -1e30f, l = 0.f, a0 = 0.f, a1 = 0.f;
    const float scale = 0.125f;  // 1/sqrt(64)

    for (int k = 0; k <= q; k++) {
        const float* krow = base + (size_t)k * (3 * DM) + DM + h * HD;
        float s = q0 * krow[lane] + q1 * krow[lane + 32];
#pragma unroll
        for (int o = 16; o > 0; o >>= 1)
            s += __shfl_xor_sync(0xffffffffu, s, o);
        s *= scale;
        float mn = fmaxf(m, s);
        float c  = __expf(m - mn);
        float p  = __expf(s - mn);
        const float* vrow = base + (size_t)k * (3 * DM) + 2 * DM + h * HD;
        l  = l  * c + p;
        a0 = a0 * c + p * vrow[lane];
        a1 = a1 * c + p * vrow[lane + 32];
        m = mn;
    }
    float inv = 1.f / l;
    float* yo = g_y + (size_t)(b * TT + q) * DM + h * HD;
    yo[lane]      = a0 * inv;
    yo[lane + 32] = a1 * inv;
}

// ---------------------------------------------------------------------------
// Launch orchestration (graph-capturable: kernel launches only)
// ---------------------------------------------------------------------------
extern "C" void kernel_launch(void* const* d_in, const int* in_sizes, int n_in,
                              void* d_out, int out_size) {
    const float* wte    = (const float*)d_in[0];
    const float* wpe    = (const float*)d_in[1];
    const float* ln1_w  = (const float*)d_in[2];
    const float* ln1_b  = (const float*)d_in[3];
    const float* attn_w = (const float*)d_in[4];
    const float* attn_b = (const float*)d_in[5];
    const float* proj_w = (const float*)d_in[6];
    const float* proj_b = (const float*)d_in[7];
    const float* ln2_w  = (const float*)d_in[8];
    const float* ln2_b  = (const float*)d_in[9];
    const float* fc_w   = (const float*)d_in[10];
    const float* fc_b   = (const float*)d_in[11];
    const float* fc2_w  = (const float*)d_in[12];
    const float* fc2_b  = (const float*)d_in[13];
    const float* lnf_w  = (const float*)d_in[14];
    const float* lnf_b  = (const float*)d_in[15];
    const int*   idx    = (const int*)d_in[16];
    float* out = (float*)d_out;

    float *x, *h, *qkv, *y, *ffn, *wteT;
    cudaGetSymbolAddress((void**)&x,    g_x);
    cudaGetSymbolAddress((void**)&h,    g_h);
    cudaGetSymbolAddress((void**)&qkv,  g_qkv);
    cudaGetSymbolAddress((void**)&y,    g_y);
    cudaGetSymbolAddress((void**)&ffn,  g_ffn);
    cudaGetSymbolAddress((void**)&wteT, g_wteT);

    gpt_embed_kernel<<<BT * DM / 256, 256>>>(wte, wpe, idx);
    gpt_transpose_kernel<<<dim3(VV / 32, DM / 32), dim3(32, 8)>>>(wte);

    for (int l = 0; l < NL; l++) {
        gpt_ln_kernel<<<BT / 8, 256>>>(x, ln1_w + l * DM, ln1_b + l * DM, h);
        gpt_gemm_kernel<1><<<dim3(3 * DM / 128, BT / 128), 256>>>(
            h, attn_w + (size_t)l * DM * 3 * DM, attn_b + l * 3 * DM,
            nullptr, qkv, BT, 3 * DM, DM);
        gpt_attn_kernel<<<BT * NH / 8, 256>>>();
        gpt_gemm_kernel<2><<<dim3(DM / 128, BT / 128), 256>>>(
            y, proj_w + (size_t)l * DM * DM, proj_b + l * DM,
            x, x, BT, DM, DM);
        gpt_ln_kernel<<<BT / 8, 256>>>(x, ln2_w + l * DM, ln2_b + l * DM, h);
        gpt_gemm_kernel<3><<<dim3(4 * DM / 128, BT / 128), 256>>>(
            h, fc_w + (size_t)l * DM * 4 * DM, fc_b + l * 4 * DM,
            nullptr, ffn, BT, 4 * DM, DM);
        gpt_gemm_kernel<2><<<dim3(DM / 128, BT / 128), 256>>>(
            ffn, fc2_w + (size_t)l * 4 * DM * DM, fc2_b + l * DM,
            x, x, BT, DM, 4 * DM);
    }

    gpt_ln_kernel<<<BT / 8, 256>>>(x, lnf_w, lnf_b, h);
    gpt_gemm_kernel<0><<<dim3(VV / 128, BT / 128), 256>>>(
        h, wteT, nullptr, nullptr, out, BT, VV, DM);
}

// round 17
// speedup vs baseline: 1.5523x; 1.5523x over previous
#include <cuda_runtime.h>
#include <math.h>
#include <stdint.h>

// Problem constants
#define NL 4
#define NH 8
#define DM 512
#define HD 64
#define TT 2048
#define BB 2
#define VV 32000
#define BT (BB*TT)          // 4096 rows
#define EPSF 1e-5f

// ---------------------------------------------------------------------------
// Scratch (device globals; no runtime allocation allowed)
// ---------------------------------------------------------------------------
__device__ float g_x[BT * DM];            // residual stream
__device__ float g_h[BT * DM];            // layernorm output
__device__ float g_qkv[BT * 3 * DM];      // qkv projections
__device__ float g_y[BT * DM];            // attention output
__device__ float g_ffn[BT * 4 * DM];      // MLP hidden
__device__ float g_wteT[(size_t)DM * VV]; // transposed embedding for lm head

// ---------------------------------------------------------------------------
// Helpers
// ---------------------------------------------------------------------------
__device__ __forceinline__ float to_tf32(float x) {
    uint32_t u;
    asm("cvt.rna.tf32.f32 %0, %1;" : "=r"(u) : "f"(x));
    return __uint_as_float(u);
}

__device__ __forceinline__ void mma_tf32(float& d0, float& d1, float& d2, float& d3,
                                         uint32_t a0, uint32_t a1, uint32_t a2, uint32_t a3,
                                         uint32_t b0, uint32_t b1) {
    asm volatile(
        "mma.sync.aligned.m16n8k8.row.col.f32.tf32.tf32.f32 "
        "{%0,%1,%2,%3}, {%4,%5,%6,%7}, {%8,%9}, {%0,%1,%2,%3};\n"
        : "+f"(d0), "+f"(d1), "+f"(d2), "+f"(d3)
        : "r"(a0), "r"(a1), "r"(a2), "r"(a3), "r"(b0), "r"(b1));
}

__device__ __forceinline__ float gelu_exact(float v) {
    return 0.5f * v * (1.0f + erff(v * 0.70710678118654752f));
}

// ---------------------------------------------------------------------------
// Embedding: x[b,t,:] = wte[idx[b,t],:] + wpe[t,:]
// ---------------------------------------------------------------------------
__global__ void gpt_embed_kernel(const float* __restrict__ wte,
                                 const float* __restrict__ wpe,
                                 const int* __restrict__ idx) {
    int i = blockIdx.x * 256 + threadIdx.x;      // over BT*DM
    int d  = i & (DM - 1);
    int bt = i >> 9;                              // /512
    int t  = bt & (TT - 1);
    g_x[i] = wte[(size_t)idx[bt] * DM + d] + wpe[t * DM + d];
}

// ---------------------------------------------------------------------------
// Transpose wte [V,D] -> wteT [D,V]
// ---------------------------------------------------------------------------
__global__ void gpt_transpose_kernel(const float* __restrict__ in) {
    __shared__ float tile[32][33];
    int v0 = blockIdx.x * 32, d0 = blockIdx.y * 32;
    int tx = threadIdx.x, ty = threadIdx.y;       // (32, 8)
#pragma unroll
    for (int j = 0; j < 32; j += 8)
        tile[ty + j][tx] = in[(size_t)(v0 + ty + j) * DM + d0 + tx];
    __syncthreads();
#pragma unroll
    for (int j = 0; j < 32; j += 8)
        g_wteT[(size_t)(d0 + ty + j) * VV + v0 + tx] = tile[tx][ty + j];
}

// ---------------------------------------------------------------------------
// LayerNorm: one warp per row of 512 (float4 x 4 per lane)
// ---------------------------------------------------------------------------
__global__ void gpt_ln_kernel(const float* __restrict__ in,
                              const float* __restrict__ w,
                              const float* __restrict__ b,
                              float* __restrict__ out) {
    int row  = blockIdx.x * 8 + (threadIdx.x >> 5);
    int lane = threadIdx.x & 31;
    const float4* p = (const float4*)(in + (size_t)row * DM);
    float4 v[4];
    float s = 0.f, s2 = 0.f;
#pragma unroll
    for (int i = 0; i < 4; i++) {
        v[i] = p[lane + i * 32];
        s  += v[i].x + v[i].y + v[i].z + v[i].w;
        s2 += v[i].x * v[i].x + v[i].y * v[i].y + v[i].z * v[i].z + v[i].w * v[i].w;
    }
#pragma unroll
    for (int o = 16; o > 0; o >>= 1) {
        s  += __shfl_xor_sync(0xffffffffu, s,  o);
        s2 += __shfl_xor_sync(0xffffffffu, s2, o);
    }
    float mu  = s  * (1.f / DM);
    float var = s2 * (1.f / DM) - mu * mu;
    float r   = rsqrtf(var + EPSF);
    float4* o4 = (float4*)(out + (size_t)row * DM);
    const float4* w4 = (const float4*)w;
    const float4* b4 = (const float4*)b;
#pragma unroll
    for (int i = 0; i < 4; i++) {
        float4 wv = w4[lane + i * 32], bv = b4[lane + i * 32], xv = v[i], yv;
        yv.x = (xv.x - mu) * r * wv.x + bv.x;
        yv.y = (xv.y - mu) * r * wv.y + bv.y;
        yv.z = (xv.z - mu) * r * wv.z + bv.z;
        yv.w = (xv.w - mu) * r * wv.w + bv.w;
        o4[lane + i * 32] = yv;
    }
}

// ---------------------------------------------------------------------------
// TF32 tensor-core GEMM: C[M,N] = A[M,K] @ B[K,N] (+ bias / + resid / gelu)
// BM=BN=128, BK=16, 256 threads = 8 warps (2x4), warp tile 64x32,
// mma.sync.m16n8k8.tf32, double-buffered smem + register prefetch.
// Smem: As[m][k] stride 20, Bs[k][n] stride 136 -> conflict-free frag reads.
// EPI: 0 = none, 1 = +bias, 2 = +bias +resid, 3 = gelu(+bias)
// ---------------------------------------------------------------------------
template<int EPI>
__global__ void __launch_bounds__(256, 2)
gpt_gemm_kernel(const float* __restrict__ A, const float* __restrict__ B,
                const float* __restrict__ bias, const float* __restrict__ resid,
                float* __restrict__ C, int M, int N, int K) {
    constexpr int BM = 128, BN = 128, BK = 16;
    constexpr int AS = 20, BS = 136;   // padded strides
    __shared__ float As[2][BM][AS];
    __shared__ float Bs[2][BK][BS];

    int tid  = threadIdx.x;
    int warp = tid >> 5, lane = tid & 31;
    int wm = warp >> 2, wn = warp & 3;            // 2 x 4 warp grid
    int g = lane >> 2, t = lane & 3;              // mma fragment coords
    int cRow = blockIdx.y, cCol = blockIdx.x;
    const float* Ag = A + (size_t)cRow * BM * K;
    const float* Bg = B + (size_t)cCol * BN;

    int aRow = tid >> 1, aCol = (tid & 1) * 8;    // A tile: 128 x 16
    int bRow = tid >> 4, bCol = (tid & 15) * 8;   // B tile: 16 x 128

    float acc[4][4][4];
#pragma unroll
    for (int mi = 0; mi < 4; mi++)
#pragma unroll
        for (int ni = 0; ni < 4; ni++)
#pragma unroll
            for (int r = 0; r < 4; r++) acc[mi][ni][r] = 0.f;

    // ---- preload tile 0 ----
    {
        const float* ap = Ag + (size_t)aRow * K + aCol;
        float4 a0 = *(const float4*)(ap);
        float4 a1 = *(const float4*)(ap + 4);
        As[0][aRow][aCol + 0] = to_tf32(a0.x); As[0][aRow][aCol + 1] = to_tf32(a0.y);
        As[0][aRow][aCol + 2] = to_tf32(a0.z); As[0][aRow][aCol + 3] = to_tf32(a0.w);
        As[0][aRow][aCol + 4] = to_tf32(a1.x); As[0][aRow][aCol + 5] = to_tf32(a1.y);
        As[0][aRow][aCol + 6] = to_tf32(a1.z); As[0][aRow][aCol + 7] = to_tf32(a1.w);
        const float* bp = Bg + (size_t)bRow * N + bCol;
        float4 b0 = *(const float4*)(bp);
        float4 b1 = *(const float4*)(bp + 4);
        Bs[0][bRow][bCol + 0] = to_tf32(b0.x); Bs[0][bRow][bCol + 1] = to_tf32(b0.y);
        Bs[0][bRow][bCol + 2] = to_tf32(b0.z); Bs[0][bRow][bCol + 3] = to_tf32(b0.w);
        Bs[0][bRow][bCol + 4] = to_tf32(b1.x); Bs[0][bRow][bCol + 5] = to_tf32(b1.y);
        Bs[0][bRow][bCol + 6] = to_tf32(b1.z); Bs[0][bRow][bCol + 7] = to_tf32(b1.w);
    }
    __syncthreads();

    int buf = 0;
    int m0w = wm * 64;
    int n0w = wn * 32;

    for (int k0 = 0; k0 < K; k0 += BK) {
        // ---- prefetch next tile into registers ----
        float4 pa0, pa1, pb0, pb1;
        bool more = (k0 + BK) < K;
        if (more) {
            const float* ap = Ag + (size_t)aRow * K + (k0 + BK) + aCol;
            pa0 = *(const float4*)(ap);
            pa1 = *(const float4*)(ap + 4);
            const float* bp = Bg + (size_t)(k0 + BK + bRow) * N + bCol;
            pb0 = *(const float4*)(bp);
            pb1 = *(const float4*)(bp + 4);
        }

        // ---- compute 2 k8-steps from smem[buf] ----
#pragma unroll
        for (int step = 0; step < 2; step++) {
            int k8 = step * 8;
            uint32_t bf[4][2];
#pragma unroll
            for (int ni = 0; ni < 4; ni++) {
                int n = n0w + ni * 8 + g;
                bf[ni][0] = __float_as_uint(Bs[buf][k8 + t][n]);
                bf[ni][1] = __float_as_uint(Bs[buf][k8 + t + 4][n]);
            }
#pragma unroll
            for (int mi = 0; mi < 4; mi++) {
                int m = m0w + mi * 16 + g;
                uint32_t a0 = __float_as_uint(As[buf][m][k8 + t]);
                uint32_t a1 = __float_as_uint(As[buf][m + 8][k8 + t]);
                uint32_t a2 = __float_as_uint(As[buf][m][k8 + t + 4]);
                uint32_t a3 = __float_as_uint(As[buf][m + 8][k8 + t + 4]);
#pragma unroll
                for (int ni = 0; ni < 4; ni++)
                    mma_tf32(acc[mi][ni][0], acc[mi][ni][1], acc[mi][ni][2], acc[mi][ni][3],
                             a0, a1, a2, a3, bf[ni][0], bf[ni][1]);
            }
        }

        // ---- store prefetched tile into the other buffer ----
        if (more) {
            int nb = buf ^ 1;
            As[nb][aRow][aCol + 0] = to_tf32(pa0.x); As[nb][aRow][aCol + 1] = to_tf32(pa0.y);
            As[nb][aRow][aCol + 2] = to_tf32(pa0.z); As[nb][aRow][aCol + 3] = to_tf32(pa0.w);
            As[nb][aRow][aCol + 4] = to_tf32(pa1.x); As[nb][aRow][aCol + 5] = to_tf32(pa1.y);
            As[nb][aRow][aCol + 6] = to_tf32(pa1.z); As[nb][aRow][aCol + 7] = to_tf32(pa1.w);
            Bs[nb][bRow][bCol + 0] = to_tf32(pb0.x); Bs[nb][bRow][bCol + 1] = to_tf32(pb0.y);
            Bs[nb][bRow][bCol + 2] = to_tf32(pb0.z); Bs[nb][bRow][bCol + 3] = to_tf32(pb0.w);
            Bs[nb][bRow][bCol + 4] = to_tf32(pb1.x); Bs[nb][bRow][bCol + 5] = to_tf32(pb1.y);
            Bs[nb][bRow][bCol + 6] = to_tf32(pb1.z); Bs[nb][bRow][bCol + 7] = to_tf32(pb1.w);
            __syncthreads();
        }
        buf ^= 1;
    }

    // ---- epilogue: fragment layout c0:(g, 2t) c1:(g, 2t+1) c2:(g+8, 2t) c3:(g+8, 2t+1)
    int bm = cRow * BM + m0w;
    int bn = cCol * BN + n0w;
#pragma unroll
    for (int mi = 0; mi < 4; mi++) {
        int r0 = bm + mi * 16 + g;
        int r1 = r0 + 8;
#pragma unroll
        for (int ni = 0; ni < 4; ni++) {
            int n = bn + ni * 8 + 2 * t;
            float2 v0 = make_float2(acc[mi][ni][0], acc[mi][ni][1]);
            float2 v1 = make_float2(acc[mi][ni][2], acc[mi][ni][3]);
            if (EPI >= 1) {
                float2 bv = *(const float2*)(bias + n);
                v0.x += bv.x; v0.y += bv.y;
                v1.x += bv.x; v1.y += bv.y;
            }
            if (EPI == 2) {
                float2 r0v = *(const float2*)(resid + (size_t)r0 * N + n);
                float2 r1v = *(const float2*)(resid + (size_t)r1 * N + n);
                v0.x += r0v.x; v0.y += r0v.y;
                v1.x += r1v.x; v1.y += r1v.y;
            }
            if (EPI == 3) {
                v0.x = gelu_exact(v0.x); v0.y = gelu_exact(v0.y);
                v1.x = gelu_exact(v1.x); v1.y = gelu_exact(v1.y);
            }
            *(float2*)(C + (size_t)r0 * N + n) = v0;
            *(float2*)(C + (size_t)r1 * N + n) = v1;
        }
    }
}

// ---------------------------------------------------------------------------
// Causal attention, warp per query row, online softmax.
// 2 keys per iteration: independent shuffle-reduce chains (ILP on SHFL
// latency), then two sequential online-softmax updates (exact same math).
// qkv row layout: [q(0..511) | k(512..1023) | v(1024..1535)], head h at h*64.
// ---------------------------------------------------------------------------
__global__ void gpt_attn_kernel() {
    int gw   = (blockIdx.x * blockDim.x + threadIdx.x) >> 5;
    int lane = threadIdx.x & 31;
    int q  = gw & (TT - 1);
    int bh = gw >> 11;            // TT = 2048
    int h  = bh & (NH - 1);
    int b  = bh >> 3;

    const float* base = g_qkv + (size_t)b * TT * (3 * DM);
    const float* qrow = base + (size_t)q * (3 * DM) + h * HD;
    float2 qv = *(const float2*)(qrow + lane * 2);

    float m = -1e30f, l = 0.f;
    float2 a = make_float2(0.f, 0.f);
    const float scale = 0.125f;  // 1/sqrt(64)

    int k = 0;
    for (; k + 1 <= q; k += 2) {
        const float* k0row = base + (size_t)k * (3 * DM) + DM + h * HD;
        const float* k1row = k0row + 3 * DM;
        float2 k0v = *(const float2*)(k0row + lane * 2);
        float2 k1v = *(const float2*)(k1row + lane * 2);
        float s0 = qv.x * k0v.x + qv.y * k0v.y;
        float s1 = qv.x * k1v.x + qv.y * k1v.y;
#pragma unroll
        for (int o = 16; o > 0; o >>= 1) {
            s0 += __shfl_xor_sync(0xffffffffu, s0, o);
            s1 += __shfl_xor_sync(0xffffffffu, s1, o);
        }
        s0 *= scale; s1 *= scale;
        const float* v0row = base + (size_t)k * (3 * DM) + 2 * DM + h * HD;
        const float* v1row = v0row + 3 * DM;
        float2 v0v = *(const float2*)(v0row + lane * 2);
        float2 v1v = *(const float2*)(v1row + lane * 2);
        // update with s0
        float mn = fmaxf(m, s0);
        float c  = __expf(m - mn);
        float p  = __expf(s0 - mn);
        l   = l   * c + p;
        a.x = a.x * c + p * v0v.x;
        a.y = a.y * c + p * v0v.y;
        m = mn;
        // update with s1
        mn = fmaxf(m, s1);
        c  = __expf(m - mn);
        p  = __expf(s1 - mn);
        l   = l   * c + p;
        a.x = a.x * c + p * v1v.x;
        a.y = a.y * c + p * v1v.y;
        m = mn;
    }
    if (k <= q) {
        const float* krow = base + (size_t)k * (3 * DM) + DM + h * HD;
        float2 kv = *(const float2*)(krow + lane * 2);
        float s = qv.x * kv.x + qv.y * kv.y;
#pragma unroll
        for (int o = 16; o > 0; o >>= 1)
            s += __shfl_xor_sync(0xffffffffu, s, o);
        s *= scale;
        float mn = fmaxf(m, s);
        float c  = __expf(m - mn);
        float p  = __expf(s - mn);
        const float* vrow = base + (size_t)k * (3 * DM) + 2 * DM + h * HD;
        float2 vv = *(const float2*)(vrow + lane * 2);
        l   = l   * c + p;
        a.x = a.x * c + p * vv.x;
        a.y = a.y * c + p * vv.y;
        m = mn;
    }
    float inv = 1.f / l;
    float* yo = g_y + (size_t)(b * TT + q) * DM + h * HD;
    *(float2*)(yo + lane * 2) = make_float2(a.x * inv, a.y * inv);
}

// ---------------------------------------------------------------------------
// Launch orchestration (graph-capturable: kernel launches only)
// ---------------------------------------------------------------------------
extern "C" void kernel_launch(void* const* d_in, const int* in_sizes, int n_in,
                              void* d_out, int out_size) {
    const float* wte    = (const float*)d_in[0];
    const float* wpe    = (const float*)d_in[1];
    const float* ln1_w  = (const float*)d_in[2];
    const float* ln1_b  = (const float*)d_in[3];
    const float* attn_w = (const float*)d_in[4];
    const float* attn_b = (const float*)d_in[5];
    const float* proj_w = (const float*)d_in[6];
    const float* proj_b = (const float*)d_in[7];
    const float* ln2_w  = (const float*)d_in[8];
    const float* ln2_b  = (const float*)d_in[9];
    const float* fc_w   = (const float*)d_in[10];
    const float* fc_b   = (const float*)d_in[11];
    const float* fc2_w  = (const float*)d_in[12];
    const float* fc2_b  = (const float*)d_in[13];
    const float* lnf_w  = (const float*)d_in[14];
    const float* lnf_b  = (const float*)d_in[15];
    const int*   idx    = (const int*)d_in[16];
    float* out = (float*)d_out;

    float *x, *h, *qkv, *y, *ffn, *wteT;
    cudaGetSymbolAddress((void**)&x,    g_x);
    cudaGetSymbolAddress((void**)&h,    g_h);
    cudaGetSymbolAddress((void**)&qkv,  g_qkv);
    cudaGetSymbolAddress((void**)&y,    g_y);
    cudaGetSymbolAddress((void**)&ffn,  g_ffn);
    cudaGetSymbolAddress((void**)&wteT, g_wteT);

    gpt_embed_kernel<<<BT * DM / 256, 256>>>(wte, wpe, idx);
    gpt_transpose_kernel<<<dim3(VV / 32, DM / 32), dim3(32, 8)>>>(wte);

    for (int l = 0; l < NL; l++) {
        gpt_ln_kernel<<<BT / 8, 256>>>(x, ln1_w + l * DM, ln1_b + l * DM, h);
        gpt_gemm_kernel<1><<<dim3(3 * DM / 128, BT / 128), 256>>>(
            h, attn_w + (size_t)l * DM * 3 * DM, attn_b + l * 3 * DM,
            nullptr, qkv, BT, 3 * DM, DM);
        gpt_attn_kernel<<<BT * NH / 8, 256>>>();
        gpt_gemm_kernel<2><<<dim3(DM / 128, BT / 128), 256>>>(
            y, proj_w + (size_t)l * DM * DM, proj_b + l * DM,
            x, x, BT, DM, DM);
        gpt_ln_kernel<<<BT / 8, 256>>>(x, ln2_w + l * DM, ln2_b + l * DM, h);
        gpt_gemm_kernel<3><<<dim3(4 * DM / 128, BT / 128), 256>>>(
            h, fc_w + (size_t)l * DM * 4 * DM, fc_b + l * 4 * DM,
            nullptr, ffn, BT, 4 * DM, DM);
        gpt_gemm_kernel<2><<<dim3(DM / 128, BT / 128), 256>>>(
            ffn, fc2_w + (size_t)l * 4 * DM * DM, fc2_b + l * DM,
            x, x, BT, DM, 4 * DM);
    }

    gpt_ln_kernel<<<BT / 8, 256>>>(x, lnf_w, lnf_b, h);
    gpt_gemm_kernel<0><<<dim3(VV / 128, BT / 128), 256>>>(
        h, wteT, nullptr, nullptr, out, BT, VV, DM);
}